// round 1
// baseline (speedup 1.0000x reference)
#include <cuda_runtime.h>
#include <math.h>

#define NN   65536
#define EE   1048576
#define NGR  64
#define DIN  256
#define DH   256
#define DOUT 128
#define EPS_LN 1e-5f

// ---------------- device scratch (no allocations allowed) ----------------
__device__ float g_bufY[(size_t)NN * DH];   // GEMM output
__device__ float g_bufH[(size_t)NN * DH];   // aggregated hidden
__device__ float g_dis[NN];                 // degree, then rsqrt(degree)
__device__ int   g_cnt[NN];                 // in-degree (excl self loop)
__device__ int   g_rowstart[NN];            // CSR row starts
__device__ int   g_fill[NN];                // scatter fill counters
__device__ int   g_srcs[EE];                // edge srcs sorted by dst
__device__ int   g_part[64];                // scan partials
__device__ float g_gcnt[NGR];               // nodes per graph

// ---------------- init ----------------
__global__ void k_init(float* pooled) {
    int i = blockIdx.x * blockDim.x + threadIdx.x;
    if (i < NN) { g_dis[i] = 1.0f; g_cnt[i] = 0; g_fill[i] = 0; }
    if (i < NGR * DOUT) pooled[i] = 0.0f;
    if (i < NGR) g_gcnt[i] = 0.0f;
}

// ---------------- degree + per-dst counts ----------------
__global__ void k_deg(const int* __restrict__ ei) {
    int e = blockIdx.x * blockDim.x + threadIdx.x;
    if (e < EE) {
        int d = ei[EE + e];
        atomicAdd(&g_dis[d], 1.0f);
        atomicAdd(&g_cnt[d], 1);
    }
}

__global__ void k_rsqrt_deg() {
    int i = blockIdx.x * blockDim.x + threadIdx.x;
    if (i < NN) g_dis[i] = rsqrtf(g_dis[i]);
}

// ---------------- block scan (N = 64 * 1024) ----------------
__global__ void k_scan1() {
    __shared__ int sh[1024];
    int t = threadIdx.x;
    int i = blockIdx.x * 1024 + t;
    int v = g_cnt[i];
    sh[t] = v; __syncthreads();
    for (int off = 1; off < 1024; off <<= 1) {
        int a = (t >= off) ? sh[t - off] : 0;
        __syncthreads();
        sh[t] += a;
        __syncthreads();
    }
    g_rowstart[i] = sh[t] - v;          // exclusive within block
    if (t == 1023) g_part[blockIdx.x] = sh[t];
}

__global__ void k_scan2() {
    if (threadIdx.x == 0) {
        int run = 0;
        for (int b = 0; b < 64; b++) { int v = g_part[b]; g_part[b] = run; run += v; }
    }
}

__global__ void k_scan3() {
    int i = blockIdx.x * blockDim.x + threadIdx.x;
    if (i < NN) g_rowstart[i] += g_part[i >> 10];
}

// ---------------- scatter edges into CSR-by-dst ----------------
__global__ void k_scatter(const int* __restrict__ ei) {
    int e = blockIdx.x * blockDim.x + threadIdx.x;
    if (e < EE) {
        int s = ei[e];
        int d = ei[EE + e];
        int pos = g_rowstart[d] + atomicAdd(&g_fill[d], 1);
        g_srcs[pos] = s;
    }
}

// ---------------- nodes per graph ----------------
__global__ void k_gcount(const int* __restrict__ batch) {
    int i = blockIdx.x * blockDim.x + threadIdx.x;
    if (i < NN) atomicAdd(&g_gcnt[batch[i]], 1.0f);
}

// ---------------- SGEMM: C[M,N] = A[M,K] @ B[K,N], fp32, 128x128x8 tile ----
__global__ __launch_bounds__(256, 2)
void k_sgemm(const float* __restrict__ A, const float* __restrict__ B,
             float* __restrict__ C, int M, int K, int N) {
    __shared__ float As[8 * 132];
    __shared__ float Bs[8 * 128];
    int tid = threadIdx.x;
    int tx = tid & 15, ty = tid >> 4;
    int bx = blockIdx.x, by = blockIdx.y;

    const float* Ab = A + (size_t)(by * 128) * K;
    const float* Bb = B + bx * 128;

    int am = tid >> 1;            // 0..127 : A tile row
    int ak = (tid & 1) * 4;       // 0 or 4 : A tile col chunk
    int brow = tid >> 5;          // 0..7   : B tile row
    int bcol = (tid & 31) * 4;    // 0..124 : B tile col

    float acc[8][8];
    #pragma unroll
    for (int i = 0; i < 8; i++)
        #pragma unroll
        for (int j = 0; j < 8; j++) acc[i][j] = 0.0f;

    for (int k0 = 0; k0 < K; k0 += 8) {
        float4 a4 = *reinterpret_cast<const float4*>(Ab + (size_t)am * K + k0 + ak);
        float4 b4 = *reinterpret_cast<const float4*>(Bb + (size_t)(k0 + brow) * N + bcol);
        As[(ak + 0) * 132 + am] = a4.x;
        As[(ak + 1) * 132 + am] = a4.y;
        As[(ak + 2) * 132 + am] = a4.z;
        As[(ak + 3) * 132 + am] = a4.w;
        *reinterpret_cast<float4*>(&Bs[brow * 128 + bcol]) = b4;
        __syncthreads();
        #pragma unroll
        for (int k = 0; k < 8; k++) {
            float ra[8], rb[8];
            #pragma unroll
            for (int j = 0; j < 8; j++) ra[j] = As[k * 132 + ty * 8 + j];
            #pragma unroll
            for (int j = 0; j < 8; j++) rb[j] = Bs[k * 128 + tx * 8 + j];
            #pragma unroll
            for (int ii = 0; ii < 8; ii++)
                #pragma unroll
                for (int jj = 0; jj < 8; jj++)
                    acc[ii][jj] = fmaf(ra[ii], rb[jj], acc[ii][jj]);
        }
        __syncthreads();
    }

    float* Cb = C + (size_t)(by * 128 + ty * 8) * N + bx * 128 + tx * 8;
    #pragma unroll
    for (int ii = 0; ii < 8; ii++) {
        float4 v0 = make_float4(acc[ii][0], acc[ii][1], acc[ii][2], acc[ii][3]);
        float4 v1 = make_float4(acc[ii][4], acc[ii][5], acc[ii][6], acc[ii][7]);
        *reinterpret_cast<float4*>(Cb + (size_t)ii * N)     = v0;
        *reinterpret_cast<float4*>(Cb + (size_t)ii * N + 4) = v1;
    }
}

// ---------------- aggregate + bias + relu + layernorm (D = 256) ----------
__global__ void k_agg_ln(const float* __restrict__ Y, float* __restrict__ H,
                         const float* __restrict__ bias,
                         const float* __restrict__ gam,
                         const float* __restrict__ bet) {
    __shared__ float sh[256];
    int i = blockIdx.x;
    int d = threadIdx.x;
    float disi = g_dis[i];
    int s0 = g_rowstart[i];
    int c  = g_cnt[i];

    float acc = disi * Y[(size_t)i * DH + d];   // self loop (disi^2 * Yself after outer *disi)
    int k = 0;
    for (; k + 4 <= c; k += 4) {
        int sa = g_srcs[s0 + k + 0];
        int sb = g_srcs[s0 + k + 1];
        int sc = g_srcs[s0 + k + 2];
        int sd = g_srcs[s0 + k + 3];
        float wa = g_dis[sa], wb = g_dis[sb], wc = g_dis[sc], wd = g_dis[sd];
        float ya = Y[(size_t)sa * DH + d];
        float yb = Y[(size_t)sb * DH + d];
        float yc = Y[(size_t)sc * DH + d];
        float yd = Y[(size_t)sd * DH + d];
        acc = fmaf(wa, ya, acc);
        acc = fmaf(wb, yb, acc);
        acc = fmaf(wc, yc, acc);
        acc = fmaf(wd, yd, acc);
    }
    for (; k < c; k++) {
        int s = g_srcs[s0 + k];
        acc = fmaf(g_dis[s], Y[(size_t)s * DH + d], acc);
    }
    float v = fmaf(disi, acc, bias[d]);
    v = fmaxf(v, 0.0f);

    // layernorm over 256 features
    sh[d] = v; __syncthreads();
    for (int off = 128; off > 0; off >>= 1) {
        if (d < off) sh[d] += sh[d + off];
        __syncthreads();
    }
    float mean = sh[0] * (1.0f / 256.0f);
    __syncthreads();
    float dv = v - mean;
    sh[d] = dv * dv; __syncthreads();
    for (int off = 128; off > 0; off >>= 1) {
        if (d < off) sh[d] += sh[d + off];
        __syncthreads();
    }
    float var = sh[0] * (1.0f / 256.0f);
    float r = rsqrtf(var + EPS_LN);
    H[(size_t)i * DH + d] = fmaf(dv * r, gam[d], bet[d]);
}

// ---------------- final aggregate + bias + output + pool accumulate ------
__global__ void k_agg_out(const float* __restrict__ Y,
                          const float* __restrict__ bias,
                          const int* __restrict__ batch,
                          float* __restrict__ out_h,
                          float* __restrict__ pooled) {
    int i = blockIdx.x;
    int d = threadIdx.x;   // 128
    float disi = g_dis[i];
    int s0 = g_rowstart[i];
    int c  = g_cnt[i];

    float acc = disi * Y[(size_t)i * DOUT + d];
    int k = 0;
    for (; k + 4 <= c; k += 4) {
        int sa = g_srcs[s0 + k + 0];
        int sb = g_srcs[s0 + k + 1];
        int sc = g_srcs[s0 + k + 2];
        int sd = g_srcs[s0 + k + 3];
        float wa = g_dis[sa], wb = g_dis[sb], wc = g_dis[sc], wd = g_dis[sd];
        float ya = Y[(size_t)sa * DOUT + d];
        float yb = Y[(size_t)sb * DOUT + d];
        float yc = Y[(size_t)sc * DOUT + d];
        float yd = Y[(size_t)sd * DOUT + d];
        acc = fmaf(wa, ya, acc);
        acc = fmaf(wb, yb, acc);
        acc = fmaf(wc, yc, acc);
        acc = fmaf(wd, yd, acc);
    }
    for (; k < c; k++) {
        int s = g_srcs[s0 + k];
        acc = fmaf(g_dis[s], Y[(size_t)s * DOUT + d], acc);
    }
    float v = fmaf(disi, acc, bias[d]);
    out_h[(size_t)i * DOUT + d] = v;
    atomicAdd(&pooled[(size_t)batch[i] * DOUT + d], v);
}

// ---------------- pooled divide ----------------
__global__ void k_pool_div(float* __restrict__ pooled) {
    int i = blockIdx.x * blockDim.x + threadIdx.x;
    if (i < NGR * DOUT) {
        float cnt = g_gcnt[i >> 7];
        pooled[i] = pooled[i] / fmaxf(cnt, 1.0f);
    }
}

// ---------------- host ----------------
extern "C" void kernel_launch(void* const* d_in, const int* in_sizes, int n_in,
                              void* d_out, int out_size) {
    const float* x    = (const float*)d_in[0];
    const int*   ei   = (const int*)d_in[1];
    const int*   bat  = (const int*)d_in[2];
    const float* W1   = (const float*)d_in[3];
    const float* b1   = (const float*)d_in[4];
    const float* g1   = (const float*)d_in[5];
    const float* be1  = (const float*)d_in[6];
    const float* W2   = (const float*)d_in[7];
    const float* b2   = (const float*)d_in[8];
    const float* g2   = (const float*)d_in[9];
    const float* be2  = (const float*)d_in[10];
    const float* W3   = (const float*)d_in[11];
    const float* b3   = (const float*)d_in[12];

    float* out_h    = (float*)d_out;
    float* out_pool = out_h + (size_t)NN * DOUT;

    float* pY = nullptr;
    float* pH = nullptr;
    cudaGetSymbolAddress((void**)&pY, g_bufY);
    cudaGetSymbolAddress((void**)&pH, g_bufH);

    // graph preprocessing
    k_init<<<NN / 256, 256>>>(out_pool);
    k_deg<<<EE / 256, 256>>>(ei);
    k_rsqrt_deg<<<NN / 256, 256>>>();
    k_scan1<<<64, 1024>>>();
    k_scan2<<<1, 32>>>();
    k_scan3<<<NN / 256, 256>>>();
    k_scatter<<<EE / 256, 256>>>(ei);
    k_gcount<<<NN / 256, 256>>>(bat);

    // layer 1: conv -> relu -> ln
    k_sgemm<<<dim3(DH / 128, NN / 128), 256>>>(x, W1, pY, NN, DIN, DH);
    k_agg_ln<<<NN, 256>>>(pY, pH, b1, g1, be1);

    // layer 2: conv -> relu -> ln
    k_sgemm<<<dim3(DH / 128, NN / 128), 256>>>(pH, W2, pY, NN, DH, DH);
    k_agg_ln<<<NN, 256>>>(pY, pH, b2, g2, be2);

    // layer 3: conv only + pool
    k_sgemm<<<dim3(DOUT / 128, NN / 128), 256>>>(pH, W3, pY, NN, DH, DOUT);
    k_agg_out<<<NN, 128>>>(pY, b3, bat, out_h, out_pool);
    k_pool_div<<<(NGR * DOUT + 255) / 256, 256>>>(out_pool);
}

// round 3
// speedup vs baseline: 1.8298x; 1.8298x over previous
#include <cuda_runtime.h>
#include <cuda_bf16.h>
#include <math.h>
#include <stdint.h>

#define NN   65536
#define EE   1048576
#define NGR  64
#define DIN  256
#define DH   256
#define DOUT 128
#define EPS_LN 1e-5f

// ---------------- device scratch (no allocations allowed) ----------------
__device__ float g_bufY[(size_t)NN * DH];            // GEMM output (fp32)
__device__ __nv_bfloat16 g_A1[(size_t)NN * DH];      // GEMM input split hi
__device__ __nv_bfloat16 g_A2[(size_t)NN * DH];      // GEMM input split lo
__device__ __nv_bfloat16 g_Wt1a[256 * 256], g_Wt1b[256 * 256];
__device__ __nv_bfloat16 g_Wt2a[256 * 256], g_Wt2b[256 * 256];
__device__ __nv_bfloat16 g_Wt3a[128 * 256], g_Wt3b[128 * 256];
__device__ float g_dis[NN];
__device__ int   g_cnt[NN];
__device__ int   g_rowstart[NN];
__device__ int   g_fill[NN];
__device__ int   g_srcs[EE];
__device__ int   g_part[64];
__device__ float g_gcnt[NGR];

// ======================= helpers ========================================
__device__ __forceinline__ uint32_t smem_u32(const void* p) {
    uint32_t a;
    asm("{ .reg .u64 t; cvta.to.shared.u64 t, %1; cvt.u32.u64 %0, t; }" : "=r"(a) : "l"(p));
    return a;
}

__device__ __forceinline__ void ldmx4(uint32_t* r, uint32_t addr) {
    asm volatile("ldmatrix.sync.aligned.m8n8.x4.shared.b16 {%0,%1,%2,%3}, [%4];"
                 : "=r"(r[0]), "=r"(r[1]), "=r"(r[2]), "=r"(r[3]) : "r"(addr));
}

__device__ __forceinline__ void mma16816(float* d, const uint32_t* a, uint32_t b0, uint32_t b1) {
    asm volatile(
        "mma.sync.aligned.m16n8k16.row.col.f32.bf16.bf16.f32 "
        "{%0,%1,%2,%3}, {%4,%5,%6,%7}, {%8,%9}, {%0,%1,%2,%3};"
        : "+f"(d[0]), "+f"(d[1]), "+f"(d[2]), "+f"(d[3])
        : "r"(a[0]), "r"(a[1]), "r"(a[2]), "r"(a[3]), "r"(b0), "r"(b1));
}

__device__ __forceinline__ void bsplit(float v, __nv_bfloat16& h, __nv_bfloat16& l) {
    h = __float2bfloat16(v);
    l = __float2bfloat16(v - __bfloat162float(h));
}

// ---------------- split W (all 3 layers, transposed to [N,K]) ------------
__global__ void k_splitW(const float* __restrict__ W1, const float* __restrict__ W2,
                         const float* __restrict__ W3) {
    int l = blockIdx.y;
    int Nl = (l == 2) ? 128 : 256;
    int id = blockIdx.x * 256 + threadIdx.x;
    if (id >= Nl * 256) return;
    int n = id >> 8, k = id & 255;
    const float* W = (l == 0) ? W1 : (l == 1) ? W2 : W3;
    float v = W[k * Nl + n];
    __nv_bfloat16 h, lo; bsplit(v, h, lo);
    if (l == 0) { g_Wt1a[id] = h; g_Wt1b[id] = lo; }
    else if (l == 1) { g_Wt2a[id] = h; g_Wt2b[id] = lo; }
    else { g_Wt3a[id] = h; g_Wt3b[id] = lo; }
}

// ---------------- split x ------------------------------------------------
__global__ void k_splitX(const float* __restrict__ X) {
    int i = blockIdx.x * blockDim.x + threadIdx.x;   // over N*256/4 float4s
    float4 v = ((const float4*)X)[i];
    __nv_bfloat16 h0, l0, h1, l1, h2, l2, h3, l3;
    bsplit(v.x, h0, l0); bsplit(v.y, h1, l1); bsplit(v.z, h2, l2); bsplit(v.w, h3, l3);
    __nv_bfloat162* p1 = (__nv_bfloat162*)g_A1;
    __nv_bfloat162* p2 = (__nv_bfloat162*)g_A2;
    p1[i * 2]     = __halves2bfloat162(h0, h1);
    p1[i * 2 + 1] = __halves2bfloat162(h2, h3);
    p2[i * 2]     = __halves2bfloat162(l0, l1);
    p2[i * 2 + 1] = __halves2bfloat162(l2, l3);
}

// ---------------- preprocessing ------------------------------------------
__global__ void k_init(float* pooled) {
    int i = blockIdx.x * blockDim.x + threadIdx.x;
    if (i < NN) { g_dis[i] = 1.0f; g_cnt[i] = 0; g_fill[i] = 0; }
    if (i < NGR * DOUT) pooled[i] = 0.0f;
    if (i < NGR) g_gcnt[i] = 0.0f;
}

__global__ void k_deg(const int* __restrict__ ei) {
    int e = blockIdx.x * blockDim.x + threadIdx.x;
    if (e < EE) {
        int d = ei[EE + e];
        atomicAdd(&g_dis[d], 1.0f);
        atomicAdd(&g_cnt[d], 1);
    }
}

__global__ void k_rsqrt_gcount(const int* __restrict__ batch) {
    int i = blockIdx.x * blockDim.x + threadIdx.x;
    if (i < NN) {
        g_dis[i] = rsqrtf(g_dis[i]);
        atomicAdd(&g_gcnt[batch[i]], 1.0f);
    }
}

__global__ void k_scan1() {
    __shared__ int sh[1024];
    int t = threadIdx.x;
    int i = blockIdx.x * 1024 + t;
    int v = g_cnt[i];
    sh[t] = v; __syncthreads();
    for (int off = 1; off < 1024; off <<= 1) {
        int a = (t >= off) ? sh[t - off] : 0;
        __syncthreads();
        sh[t] += a;
        __syncthreads();
    }
    g_rowstart[i] = sh[t] - v;
    if (t == 1023) g_part[blockIdx.x] = sh[t];
}

__global__ void k_scan2() {
    if (threadIdx.x == 0) {
        int run = 0;
        for (int b = 0; b < 64; b++) { int v = g_part[b]; g_part[b] = run; run += v; }
    }
}

__global__ void k_scan3() {
    int i = blockIdx.x * blockDim.x + threadIdx.x;
    if (i < NN) g_rowstart[i] += g_part[i >> 10];
}

__global__ void k_scatter(const int* __restrict__ ei) {
    int e = blockIdx.x * blockDim.x + threadIdx.x;
    if (e < EE) {
        int s = ei[e];
        int d = ei[EE + e];
        int pos = g_rowstart[d] + atomicAdd(&g_fill[d], 1);
        g_srcs[pos] = s;
    }
}

// ======================= HMMA bf16x3 GEMM ================================
// C[65536, NMAT] = A[65536,256] @ W[256,NMAT], splits A1,A2 / B1,B2 (B is [NMAT,256] K-major).
// Block tile 128x128x32; 8 warps (4M x 2N); warp tile 32x64.
// smem tiles [128 rows][32 bf16] = 64B/row; swizzle: 16B-chunk c ^= (row>>1)&3.
template <int NMAT>
__global__ void __launch_bounds__(256, 2)
k_gemm(const __nv_bfloat16* __restrict__ A1, const __nv_bfloat16* __restrict__ A2,
       const __nv_bfloat16* __restrict__ B1, const __nv_bfloat16* __restrict__ B2,
       float* __restrict__ C) {
    __shared__ __align__(16) __nv_bfloat16 sA1[128 * 32];
    __shared__ __align__(16) __nv_bfloat16 sA2[128 * 32];
    __shared__ __align__(16) __nv_bfloat16 sB1[128 * 32];
    __shared__ __align__(16) __nv_bfloat16 sB2[128 * 32];

    int tid = threadIdx.x;
    int lane = tid & 31;
    int wid = tid >> 5;
    int wm = wid & 3;       // warp row: wm*32
    int wn = wid >> 2;      // warp col: wn*64
    int mtile = blockIdx.y, ntile = blockIdx.x;

    float acc[2][8][4];
    #pragma unroll
    for (int i = 0; i < 2; i++)
        #pragma unroll
        for (int j = 0; j < 8; j++)
            #pragma unroll
            for (int q = 0; q < 4; q++) acc[i][j][q] = 0.0f;

    uint32_t baseA1 = smem_u32(sA1), baseA2 = smem_u32(sA2);
    uint32_t baseB1 = smem_u32(sB1), baseB2 = smem_u32(sB2);

    // ldmatrix per-lane row/chunk components
    int lrow = lane & 15;       // row within 16-row group
    int lhalf = lane >> 4;      // k-half (16B chunk selector within k16)

    const uint4* gA1 = (const uint4*)A1;
    const uint4* gA2 = (const uint4*)A2;
    const uint4* gB1 = (const uint4*)B1;
    const uint4* gB2 = (const uint4*)B2;

    #pragma unroll 1
    for (int kc = 0; kc < 8; kc++) {
        // ---- load tiles: 512 uint4 per tile, 2 per thread ----
        #pragma unroll
        for (int it = 0; it < 2; it++) {
            int idx = tid + it * 256;
            int r = idx >> 2, c = idx & 3;
            int sw = c ^ ((r >> 1) & 3);
            // A rows: global row = mtile*128 + r, uint4 idx = row*32 + kc*4 + c
            size_t ga = (size_t)(mtile * 128 + r) * 32 + kc * 4 + c;
            ((uint4*)sA1)[r * 4 + sw] = gA1[ga];
            ((uint4*)sA2)[r * 4 + sw] = gA2[ga];
            size_t gb = (size_t)(ntile * 128 + r) * 32 + kc * 4 + c;
            ((uint4*)sB1)[r * 4 + sw] = gB1[gb];
            ((uint4*)sB2)[r * 4 + sw] = gB2[gb];
        }
        __syncthreads();

        #pragma unroll
        for (int ks = 0; ks < 2; ks++) {
            // A fragments (2 m16 tiles x 2 splits)
            uint32_t a1[2][4], a2[2][4];
            #pragma unroll
            for (int mi = 0; mi < 2; mi++) {
                int row = wm * 32 + mi * 16 + lrow;
                int ch = (ks * 2 + lhalf) ^ ((row >> 1) & 3);
                uint32_t off = row * 64 + ch * 16;
                ldmx4(a1[mi], baseA1 + off);
                ldmx4(a2[mi], baseA2 + off);
            }
            // B in two n32 halves to limit register pressure
            #pragma unroll
            for (int nh = 0; nh < 2; nh++) {
                uint32_t b1[2][4], b2[2][4];
                #pragma unroll
                for (int ni2 = 0; ni2 < 2; ni2++) {
                    int row = wn * 64 + nh * 32 + ni2 * 16 + lrow;
                    int ch = (ks * 2 + lhalf) ^ ((row >> 1) & 3);
                    uint32_t off = row * 64 + ch * 16;
                    ldmx4(b1[ni2], baseB1 + off);
                    ldmx4(b2[ni2], baseB2 + off);
                }
                #pragma unroll
                for (int mi = 0; mi < 2; mi++) {
                    #pragma unroll
                    for (int ni = 0; ni < 4; ni++) {
                        int ni2 = ni >> 1, nj = ni & 1;   // frag j within x4: regs {nj, nj+2}
                        float* d = acc[mi][nh * 4 + ni];
                        mma16816(d, a1[mi], b1[ni2][nj], b1[ni2][nj + 2]);
                        mma16816(d, a1[mi], b2[ni2][nj], b2[ni2][nj + 2]);
                        mma16816(d, a2[mi], b1[ni2][nj], b1[ni2][nj + 2]);
                    }
                }
            }
        }
        __syncthreads();
    }

    // ---- epilogue: fp32 direct to C ----
    int crow0 = mtile * 128 + wm * 32 + (lane >> 2);
    int ccol0 = ntile * 128 + wn * 64 + (lane & 3) * 2;
    #pragma unroll
    for (int mi = 0; mi < 2; mi++) {
        #pragma unroll
        for (int ni = 0; ni < 8; ni++) {
            float* d = acc[mi][ni];
            int col = ccol0 + ni * 8;
            int r0 = crow0 + mi * 16;
            ((float2*)(C + (size_t)r0 * NMAT + col))[0] = make_float2(d[0], d[1]);
            ((float2*)(C + (size_t)(r0 + 8) * NMAT + col))[0] = make_float2(d[2], d[3]);
        }
    }
}

// ---------------- aggregate + bias + relu + LN, write bf16 splits --------
__global__ void __launch_bounds__(256)
k_agg_ln(const float* __restrict__ Y,
         const float* __restrict__ bias, const float* __restrict__ gam,
         const float* __restrict__ bet) {
    __shared__ float shm[4][2], shv[4][2];
    int slot = threadIdx.x >> 6;
    int q = threadIdx.x & 63;
    int node = (blockIdx.x << 2) + slot;
    float disi = g_dis[node];
    int s0 = g_rowstart[node], c = g_cnt[node];
    const float4* Yv = (const float4*)Y;

    float4 a = Yv[(size_t)node * 64 + q];
    float ax = disi * a.x, ay = disi * a.y, az = disi * a.z, aw = disi * a.w;
    int k = 0;
    for (; k + 4 <= c; k += 4) {
        int sa = g_srcs[s0 + k], sb = g_srcs[s0 + k + 1];
        int sc = g_srcs[s0 + k + 2], sd = g_srcs[s0 + k + 3];
        float wa = g_dis[sa], wb = g_dis[sb], wc = g_dis[sc], wd = g_dis[sd];
        float4 ya = Yv[(size_t)sa * 64 + q];
        float4 yb = Yv[(size_t)sb * 64 + q];
        float4 yc = Yv[(size_t)sc * 64 + q];
        float4 yd = Yv[(size_t)sd * 64 + q];
        ax = fmaf(wa, ya.x, ax); ay = fmaf(wa, ya.y, ay); az = fmaf(wa, ya.z, az); aw = fmaf(wa, ya.w, aw);
        ax = fmaf(wb, yb.x, ax); ay = fmaf(wb, yb.y, ay); az = fmaf(wb, yb.z, az); aw = fmaf(wb, yb.w, aw);
        ax = fmaf(wc, yc.x, ax); ay = fmaf(wc, yc.y, ay); az = fmaf(wc, yc.z, az); aw = fmaf(wc, yc.w, aw);
        ax = fmaf(wd, yd.x, ax); ay = fmaf(wd, yd.y, ay); az = fmaf(wd, yd.z, az); aw = fmaf(wd, yd.w, aw);
    }
    for (; k < c; k++) {
        int s = g_srcs[s0 + k];
        float w = g_dis[s];
        float4 y = Yv[(size_t)s * 64 + q];
        ax = fmaf(w, y.x, ax); ay = fmaf(w, y.y, ay); az = fmaf(w, y.z, az); aw = fmaf(w, y.w, aw);
    }
    float4 b4 = ((const float4*)bias)[q];
    float vx = fmaxf(fmaf(disi, ax, b4.x), 0.0f);
    float vy = fmaxf(fmaf(disi, ay, b4.y), 0.0f);
    float vz = fmaxf(fmaf(disi, az, b4.z), 0.0f);
    float vw = fmaxf(fmaf(disi, aw, b4.w), 0.0f);

    float s1 = vx + vy + vz + vw;
    #pragma unroll
    for (int off = 16; off > 0; off >>= 1) s1 += __shfl_down_sync(0xffffffffu, s1, off);
    if ((q & 31) == 0) shm[slot][q >> 5] = s1;
    __syncthreads();
    float mean = (shm[slot][0] + shm[slot][1]) * (1.0f / 256.0f);
    float dx = vx - mean, dy = vy - mean, dz = vz - mean, dw = vw - mean;
    float s2 = dx * dx + dy * dy + dz * dz + dw * dw;
    #pragma unroll
    for (int off = 16; off > 0; off >>= 1) s2 += __shfl_down_sync(0xffffffffu, s2, off);
    if ((q & 31) == 0) shv[slot][q >> 5] = s2;
    __syncthreads();
    float var = (shv[slot][0] + shv[slot][1]) * (1.0f / 256.0f);
    float r = rsqrtf(var + EPS_LN);
    float4 g4 = ((const float4*)gam)[q];
    float4 e4 = ((const float4*)bet)[q];
    float o0 = fmaf(dx * r, g4.x, e4.x);
    float o1 = fmaf(dy * r, g4.y, e4.y);
    float o2 = fmaf(dz * r, g4.z, e4.z);
    float o3 = fmaf(dw * r, g4.w, e4.w);

    __nv_bfloat16 h0, l0, h1, l1, h2, l2, h3, l3;
    bsplit(o0, h0, l0); bsplit(o1, h1, l1); bsplit(o2, h2, l2); bsplit(o3, h3, l3);
    __nv_bfloat162* p1 = (__nv_bfloat162*)g_A1;
    __nv_bfloat162* p2 = (__nv_bfloat162*)g_A2;
    size_t bi = (size_t)node * 128 + q * 2;
    p1[bi]     = __halves2bfloat162(h0, h1);
    p1[bi + 1] = __halves2bfloat162(h2, h3);
    p2[bi]     = __halves2bfloat162(l0, l1);
    p2[bi + 1] = __halves2bfloat162(l2, l3);
}

// ---------------- final aggregate + bias + output + pool -----------------
__global__ void __launch_bounds__(256)
k_agg_out(const float* __restrict__ Y, const float* __restrict__ bias,
          const int* __restrict__ batch, float* __restrict__ out_h,
          float* __restrict__ pooled) {
    int slot = threadIdx.x >> 5;
    int q = threadIdx.x & 31;
    int node = (blockIdx.x << 3) + slot;
    float disi = g_dis[node];
    int s0 = g_rowstart[node], c = g_cnt[node];
    const float4* Yv = (const float4*)Y;

    float4 a = Yv[(size_t)node * 32 + q];
    float ax = disi * a.x, ay = disi * a.y, az = disi * a.z, aw = disi * a.w;
    int k = 0;
    for (; k + 4 <= c; k += 4) {
        int sa = g_srcs[s0 + k], sb = g_srcs[s0 + k + 1];
        int sc = g_srcs[s0 + k + 2], sd = g_srcs[s0 + k + 3];
        float wa = g_dis[sa], wb = g_dis[sb], wc = g_dis[sc], wd = g_dis[sd];
        float4 ya = Yv[(size_t)sa * 32 + q];
        float4 yb = Yv[(size_t)sb * 32 + q];
        float4 yc = Yv[(size_t)sc * 32 + q];
        float4 yd = Yv[(size_t)sd * 32 + q];
        ax = fmaf(wa, ya.x, ax); ay = fmaf(wa, ya.y, ay); az = fmaf(wa, ya.z, az); aw = fmaf(wa, ya.w, aw);
        ax = fmaf(wb, yb.x, ax); ay = fmaf(wb, yb.y, ay); az = fmaf(wb, yb.z, az); aw = fmaf(wb, yb.w, aw);
        ax = fmaf(wc, yc.x, ax); ay = fmaf(wc, yc.y, ay); az = fmaf(wc, yc.z, az); aw = fmaf(wc, yc.w, aw);
        ax = fmaf(wd, yd.x, ax); ay = fmaf(wd, yd.y, ay); az = fmaf(wd, yd.z, az); aw = fmaf(wd, yd.w, aw);
    }
    for (; k < c; k++) {
        int s = g_srcs[s0 + k];
        float w = g_dis[s];
        float4 y = Yv[(size_t)s * 32 + q];
        ax = fmaf(w, y.x, ax); ay = fmaf(w, y.y, ay); az = fmaf(w, y.z, az); aw = fmaf(w, y.w, aw);
    }
    float4 b4 = ((const float4*)bias)[q];
    float4 v = make_float4(fmaf(disi, ax, b4.x), fmaf(disi, ay, b4.y),
                           fmaf(disi, az, b4.z), fmaf(disi, aw, b4.w));
    ((float4*)out_h)[(size_t)node * 32 + q] = v;
    float* pp = pooled + (size_t)batch[node] * DOUT + q * 4;
    atomicAdd(pp + 0, v.x);
    atomicAdd(pp + 1, v.y);
    atomicAdd(pp + 2, v.z);
    atomicAdd(pp + 3, v.w);
}

__global__ void k_pool_div(float* __restrict__ pooled) {
    int i = blockIdx.x * blockDim.x + threadIdx.x;
    if (i < NGR * DOUT) {
        float cnt = g_gcnt[i >> 7];
        pooled[i] = pooled[i] / fmaxf(cnt, 1.0f);
    }
}

// ---------------- host ---------------------------------------------------
extern "C" void kernel_launch(void* const* d_in, const int* in_sizes, int n_in,
                              void* d_out, int out_size) {
    const float* x    = (const float*)d_in[0];
    const int*   ei   = (const int*)d_in[1];
    const int*   bat  = (const int*)d_in[2];
    const float* W1   = (const float*)d_in[3];
    const float* b1   = (const float*)d_in[4];
    const float* g1   = (const float*)d_in[5];
    const float* be1  = (const float*)d_in[6];
    const float* W2   = (const float*)d_in[7];
    const float* b2   = (const float*)d_in[8];
    const float* g2   = (const float*)d_in[9];
    const float* be2  = (const float*)d_in[10];
    const float* W3   = (const float*)d_in[11];
    const float* b3   = (const float*)d_in[12];

    float* out_h    = (float*)d_out;
    float* out_pool = out_h + (size_t)NN * DOUT;

    float* pY = nullptr;
    __nv_bfloat16 *pA1 = nullptr, *pA2 = nullptr;
    __nv_bfloat16 *pW1a = nullptr, *pW1b = nullptr, *pW2a = nullptr, *pW2b = nullptr;
    __nv_bfloat16 *pW3a = nullptr, *pW3b = nullptr;
    cudaGetSymbolAddress((void**)&pY,   g_bufY);
    cudaGetSymbolAddress((void**)&pA1,  g_A1);
    cudaGetSymbolAddress((void**)&pA2,  g_A2);
    cudaGetSymbolAddress((void**)&pW1a, g_Wt1a);
    cudaGetSymbolAddress((void**)&pW1b, g_Wt1b);
    cudaGetSymbolAddress((void**)&pW2a, g_Wt2a);
    cudaGetSymbolAddress((void**)&pW2b, g_Wt2b);
    cudaGetSymbolAddress((void**)&pW3a, g_Wt3a);
    cudaGetSymbolAddress((void**)&pW3b, g_Wt3b);

    // launches 0-2: prep (gemm1 at index 3 for the profiler window)
    k_splitW<<<dim3(256, 3), 256>>>(W1, W2, W3);
    k_splitX<<<(NN * DIN / 4) / 256, 256>>>(x);
    k_init<<<NN / 256, 256>>>(out_pool);

    // 3: layer-1 GEMM (x @ W1)
    k_gemm<256><<<dim3(2, NN / 128), 256>>>(pA1, pA2, pW1a, pW1b, pY);

    // graph preprocessing (overlaps nothing, but independent of gemm output)
    k_deg<<<EE / 256, 256>>>(ei);
    k_rsqrt_gcount<<<NN / 256, 256>>>(bat);
    k_scan1<<<64, 1024>>>();
    k_scan2<<<1, 32>>>();
    k_scan3<<<NN / 256, 256>>>();
    k_scatter<<<EE / 256, 256>>>(ei);

    // layer 1 aggregate -> relu -> LN -> bf16 splits
    k_agg_ln<<<NN / 4, 256>>>(pY, b1, g1, be1);
    // layer 2
    k_gemm<256><<<dim3(2, NN / 128), 256>>>(pA1, pA2, pW2a, pW2b, pY);
    k_agg_ln<<<NN / 4, 256>>>(pY, b2, g2, be2);
    // layer 3
    k_gemm<128><<<dim3(1, NN / 128), 256>>>(pA1, pA2, pW3a, pW3b, pY);
    k_agg_out<<<NN / 8, 256>>>(pY, b3, bat, out_h, out_pool);
    k_pool_div<<<(NGR * DOUT + 255) / 256, 256>>>(out_pool);
}

// round 4
// speedup vs baseline: 2.1001x; 1.1477x over previous
#include <cuda_runtime.h>
#include <cuda_bf16.h>
#include <math.h>
#include <stdint.h>

#define NN   65536
#define EE   1048576
#define NGR  64
#define DIN  256
#define DH   256
#define DOUT 128
#define EPS_LN 1e-5f

// ---------------- device scratch ----------------
__device__ float g_bufY[(size_t)NN * DH];            // GEMM output (fp32, pre-scaled by dis)
__device__ __nv_bfloat16 g_A1[(size_t)NN * DH];      // GEMM input split hi
__device__ __nv_bfloat16 g_A2[(size_t)NN * DH];      // GEMM input split lo
__device__ __nv_bfloat16 g_Wt1a[256 * 256], g_Wt1b[256 * 256];
__device__ __nv_bfloat16 g_Wt2a[256 * 256], g_Wt2b[256 * 256];
__device__ __nv_bfloat16 g_Wt3a[128 * 256], g_Wt3b[128 * 256];
__device__ int   g_cnt[NN];          // in-degree (excl self loop); deg = cnt+1
__device__ int   g_rowstart[NN];
__device__ int   g_fill[NN];
__device__ int   g_srcs[EE];
__device__ int   g_part[64];
__device__ float g_gcnt[NGR];

// ======================= helpers ========================================
__device__ __forceinline__ uint32_t smem_u32(const void* p) {
    uint32_t a;
    asm("{ .reg .u64 t; cvta.to.shared.u64 t, %1; cvt.u32.u64 %0, t; }" : "=r"(a) : "l"(p));
    return a;
}

__device__ __forceinline__ void ldmx4(uint32_t* r, uint32_t addr) {
    asm volatile("ldmatrix.sync.aligned.m8n8.x4.shared.b16 {%0,%1,%2,%3}, [%4];"
                 : "=r"(r[0]), "=r"(r[1]), "=r"(r[2]), "=r"(r[3]) : "r"(addr));
}

__device__ __forceinline__ void mma16816(float* d, const uint32_t* a, uint32_t b0, uint32_t b1) {
    asm volatile(
        "mma.sync.aligned.m16n8k16.row.col.f32.bf16.bf16.f32 "
        "{%0,%1,%2,%3}, {%4,%5,%6,%7}, {%8,%9}, {%0,%1,%2,%3};"
        : "+f"(d[0]), "+f"(d[1]), "+f"(d[2]), "+f"(d[3])
        : "r"(a[0]), "r"(a[1]), "r"(a[2]), "r"(a[3]), "r"(b0), "r"(b1));
}

__device__ __forceinline__ void cp16(uint32_t dst, const void* src) {
    asm volatile("cp.async.cg.shared.global [%0], [%1], 16;" :: "r"(dst), "l"(src));
}
#define CP_COMMIT() asm volatile("cp.async.commit_group;" ::: "memory")
#define CP_WAIT1()  asm volatile("cp.async.wait_group 1;" ::: "memory")
#define CP_WAIT0()  asm volatile("cp.async.wait_group 0;" ::: "memory")

__device__ __forceinline__ void bsplit(float v, __nv_bfloat16& h, __nv_bfloat16& l) {
    h = __float2bfloat16(v);
    l = __float2bfloat16(v - __bfloat162float(h));
}

// ---------------- split W + zero counters/pooled -------------------------
__global__ void k_splitW_init(const float* __restrict__ W1, const float* __restrict__ W2,
                              const float* __restrict__ W3, float* pooled) {
    int l = blockIdx.y;
    int Nl = (l == 2) ? 128 : 256;
    int id = blockIdx.x * 256 + threadIdx.x;
    if (l == 0) {
        // 256 blocks x 256 thr = 65536 = NN exactly
        g_cnt[id] = 0;
        g_fill[id] = 0;
        if (id < NGR * DOUT) pooled[id] = 0.0f;
        if (id < NGR) g_gcnt[id] = 0.0f;
    }
    if (id >= Nl * 256) return;
    int n = id >> 8, k = id & 255;
    const float* W = (l == 0) ? W1 : (l == 1) ? W2 : W3;
    float v = W[k * Nl + n];
    __nv_bfloat16 h, lo; bsplit(v, h, lo);
    if (l == 0) { g_Wt1a[id] = h; g_Wt1b[id] = lo; }
    else if (l == 1) { g_Wt2a[id] = h; g_Wt2b[id] = lo; }
    else { g_Wt3a[id] = h; g_Wt3b[id] = lo; }
}

// ---------------- split x + graph-count atomics --------------------------
__global__ void k_splitX_gc(const float* __restrict__ X, const int* __restrict__ batch) {
    int i = blockIdx.x * blockDim.x + threadIdx.x;   // over N*256/4 float4s
    float4 v = ((const float4*)X)[i];
    __nv_bfloat16 h0, l0, h1, l1, h2, l2, h3, l3;
    bsplit(v.x, h0, l0); bsplit(v.y, h1, l1); bsplit(v.z, h2, l2); bsplit(v.w, h3, l3);
    __nv_bfloat162* p1 = (__nv_bfloat162*)g_A1;
    __nv_bfloat162* p2 = (__nv_bfloat162*)g_A2;
    p1[i * 2]     = __halves2bfloat162(h0, h1);
    p1[i * 2 + 1] = __halves2bfloat162(h2, h3);
    p2[i * 2]     = __halves2bfloat162(l0, l1);
    p2[i * 2 + 1] = __halves2bfloat162(l2, l3);
    if (i < NN) atomicAdd(&g_gcnt[batch[i]], 1.0f);
}

// ---------------- degree (single int atomic) -----------------------------
__global__ void k_deg(const int* __restrict__ ei) {
    int e = blockIdx.x * blockDim.x + threadIdx.x;
    if (e < EE) atomicAdd(&g_cnt[ei[EE + e]], 1);
}

__global__ void k_scan1() {
    __shared__ int sh[1024];
    int t = threadIdx.x;
    int i = blockIdx.x * 1024 + t;
    int v = g_cnt[i];
    sh[t] = v; __syncthreads();
    for (int off = 1; off < 1024; off <<= 1) {
        int a = (t >= off) ? sh[t - off] : 0;
        __syncthreads();
        sh[t] += a;
        __syncthreads();
    }
    g_rowstart[i] = sh[t] - v;
    if (t == 1023) g_part[blockIdx.x] = sh[t];
}

__global__ void k_scan2() {
    if (threadIdx.x == 0) {
        int run = 0;
        for (int b = 0; b < 64; b++) { int v = g_part[b]; g_part[b] = run; run += v; }
    }
}

__global__ void k_scan3() {
    int i = blockIdx.x * blockDim.x + threadIdx.x;
    if (i < NN) g_rowstart[i] += g_part[i >> 10];
}

__global__ void k_scatter(const int* __restrict__ ei) {
    int e = blockIdx.x * blockDim.x + threadIdx.x;
    if (e < EE) {
        int s = ei[e];
        int d = ei[EE + e];
        int pos = g_rowstart[d] + atomicAdd(&g_fill[d], 1);
        g_srcs[pos] = s;
    }
}

// ======================= HMMA bf16x3 GEMM (cp.async 2-stage) ============
// C[65536, NMAT] = dis[row] * (A[65536,256] @ W[256,NMAT])
// splits A1,A2 / B1,B2 (B is [NMAT,256] K-major). Block 128x128x32, 8 warps.
// dyn smem: [2 stages][4 tiles][128x32 bf16] = 65536 B.
template <int NMAT>
__global__ void __launch_bounds__(256, 2)
k_gemm(const __nv_bfloat16* __restrict__ A1, const __nv_bfloat16* __restrict__ A2,
       const __nv_bfloat16* __restrict__ B1, const __nv_bfloat16* __restrict__ B2,
       float* __restrict__ C) {
    extern __shared__ __align__(16) __nv_bfloat16 smem[];
    uint32_t sbase = smem_u32(smem);

    int tid = threadIdx.x;
    int lane = tid & 31;
    int wid = tid >> 5;
    int wm = wid & 3;
    int wn = wid >> 2;
    int mtile = blockIdx.y, ntile = blockIdx.x;

    float acc[2][8][4];
    #pragma unroll
    for (int i = 0; i < 2; i++)
        #pragma unroll
        for (int j = 0; j < 8; j++)
            #pragma unroll
            for (int q = 0; q < 4; q++) acc[i][j][q] = 0.0f;

    // per-thread load coordinates (2 chunks of 512 uint4 per tile)
    int r0i = tid >> 2, c0i = tid & 3;
    int r1i = (tid + 256) >> 2, c1i = (tid + 256) & 3;
    int sw0 = c0i ^ ((r0i >> 1) & 3), sw1 = c1i ^ ((r1i >> 1) & 3);
    uint32_t d0 = (r0i * 4 + sw0) * 16, d1 = (r1i * 4 + sw1) * 16;

    const uint4* pA1_0 = (const uint4*)A1 + (size_t)(mtile * 128 + r0i) * 32 + c0i;
    const uint4* pA1_1 = (const uint4*)A1 + (size_t)(mtile * 128 + r1i) * 32 + c1i;
    const uint4* pA2_0 = (const uint4*)A2 + (size_t)(mtile * 128 + r0i) * 32 + c0i;
    const uint4* pA2_1 = (const uint4*)A2 + (size_t)(mtile * 128 + r1i) * 32 + c1i;
    const uint4* pB1_0 = (const uint4*)B1 + (size_t)(ntile * 128 + r0i) * 32 + c0i;
    const uint4* pB1_1 = (const uint4*)B1 + (size_t)(ntile * 128 + r1i) * 32 + c1i;
    const uint4* pB2_0 = (const uint4*)B2 + (size_t)(ntile * 128 + r0i) * 32 + c0i;
    const uint4* pB2_1 = (const uint4*)B2 + (size_t)(ntile * 128 + r1i) * 32 + c1i;

    int lrow = lane & 15;
    int lhalf = lane >> 4;

    auto prefetch = [&](int st, int kc) {
        uint32_t sb = sbase + st * 32768;
        int ko = kc * 4;
        cp16(sb + d0,         pA1_0 + ko);
        cp16(sb + d1,         pA1_1 + ko);
        cp16(sb + 8192 + d0,  pA2_0 + ko);
        cp16(sb + 8192 + d1,  pA2_1 + ko);
        cp16(sb + 16384 + d0, pB1_0 + ko);
        cp16(sb + 16384 + d1, pB1_1 + ko);
        cp16(sb + 24576 + d0, pB2_0 + ko);
        cp16(sb + 24576 + d1, pB2_1 + ko);
    };

    prefetch(0, 0);
    CP_COMMIT();

    #pragma unroll 1
    for (int kc = 0; kc < 8; kc++) {
        if (kc < 7) {
            prefetch((kc + 1) & 1, kc + 1);
            CP_COMMIT();
            CP_WAIT1();
        } else {
            CP_WAIT0();
        }
        __syncthreads();

        uint32_t tb = sbase + (kc & 1) * 32768;
        #pragma unroll
        for (int ks = 0; ks < 2; ks++) {
            uint32_t a1[2][4], a2[2][4];
            #pragma unroll
            for (int mi = 0; mi < 2; mi++) {
                int row = wm * 32 + mi * 16 + lrow;
                int ch = (ks * 2 + lhalf) ^ ((row >> 1) & 3);
                uint32_t off = row * 64 + ch * 16;
                ldmx4(a1[mi], tb + off);
                ldmx4(a2[mi], tb + 8192 + off);
            }
            #pragma unroll
            for (int nh = 0; nh < 2; nh++) {
                uint32_t b1[2][4], b2[2][4];
                #pragma unroll
                for (int ni2 = 0; ni2 < 2; ni2++) {
                    int row = wn * 64 + nh * 32 + ni2 * 16 + lrow;
                    int ch = (ks * 2 + lhalf) ^ ((row >> 1) & 3);
                    uint32_t off = row * 64 + ch * 16;
                    ldmx4(b1[ni2], tb + 16384 + off);
                    ldmx4(b2[ni2], tb + 24576 + off);
                }
                #pragma unroll
                for (int mi = 0; mi < 2; mi++) {
                    #pragma unroll
                    for (int ni = 0; ni < 4; ni++) {
                        int ni2 = ni >> 1, nj = ni & 1;
                        float* d = acc[mi][nh * 4 + ni];
                        mma16816(d, a1[mi], b1[ni2][nj], b1[ni2][nj + 2]);
                        mma16816(d, a1[mi], b2[ni2][nj], b2[ni2][nj + 2]);
                        mma16816(d, a2[mi], b1[ni2][nj], b1[ni2][nj + 2]);
                    }
                }
            }
        }
        __syncthreads();
    }

    // ---- epilogue: scale by dis[row] = rsqrt(cnt+1), write fp32 ----
    int crow0 = mtile * 128 + wm * 32 + (lane >> 2);
    int ccol0 = ntile * 128 + wn * 64 + (lane & 3) * 2;
    float dr[2][2];
    #pragma unroll
    for (int mi = 0; mi < 2; mi++) {
        dr[mi][0] = rsqrtf((float)g_cnt[crow0 + mi * 16] + 1.0f);
        dr[mi][1] = rsqrtf((float)g_cnt[crow0 + mi * 16 + 8] + 1.0f);
    }
    #pragma unroll
    for (int mi = 0; mi < 2; mi++) {
        #pragma unroll
        for (int ni = 0; ni < 8; ni++) {
            float* d = acc[mi][ni];
            int col = ccol0 + ni * 8;
            int r0 = crow0 + mi * 16;
            ((float2*)(C + (size_t)r0 * NMAT + col))[0] =
                make_float2(d[0] * dr[mi][0], d[1] * dr[mi][0]);
            ((float2*)(C + (size_t)(r0 + 8) * NMAT + col))[0] =
                make_float2(d[2] * dr[mi][1], d[3] * dr[mi][1]);
        }
    }
}

// ---------------- aggregate (pure add) + bias + relu + LN ----------------
__global__ void __launch_bounds__(256)
k_agg_ln(const float* __restrict__ Y,
         const float* __restrict__ bias, const float* __restrict__ gam,
         const float* __restrict__ bet) {
    __shared__ float shm[4][2], shv[4][2];
    int slot = threadIdx.x >> 6;
    int q = threadIdx.x & 63;
    int node = (blockIdx.x << 2) + slot;
    int s0 = g_rowstart[node], c = g_cnt[node];
    float disi = rsqrtf((float)c + 1.0f);
    const float4* Yv = (const float4*)Y;

    float4 a = Yv[(size_t)node * 64 + q];     // self term (already dis-scaled)
    float ax = a.x, ay = a.y, az = a.z, aw = a.w;
    int k = 0;
    for (; k + 8 <= c; k += 8) {
        int s[8];
        #pragma unroll
        for (int j = 0; j < 8; j++) s[j] = g_srcs[s0 + k + j];
        float4 y[8];
        #pragma unroll
        for (int j = 0; j < 8; j++) y[j] = Yv[(size_t)s[j] * 64 + q];
        #pragma unroll
        for (int j = 0; j < 8; j++) {
            ax += y[j].x; ay += y[j].y; az += y[j].z; aw += y[j].w;
        }
    }
    for (; k < c; k++) {
        float4 y = Yv[(size_t)g_srcs[s0 + k] * 64 + q];
        ax += y.x; ay += y.y; az += y.z; aw += y.w;
    }
    float4 b4 = ((const float4*)bias)[q];
    float vx = fmaxf(fmaf(disi, ax, b4.x), 0.0f);
    float vy = fmaxf(fmaf(disi, ay, b4.y), 0.0f);
    float vz = fmaxf(fmaf(disi, az, b4.z), 0.0f);
    float vw = fmaxf(fmaf(disi, aw, b4.w), 0.0f);

    float s1 = vx + vy + vz + vw;
    #pragma unroll
    for (int off = 16; off > 0; off >>= 1) s1 += __shfl_down_sync(0xffffffffu, s1, off);
    if ((q & 31) == 0) shm[slot][q >> 5] = s1;
    __syncthreads();
    float mean = (shm[slot][0] + shm[slot][1]) * (1.0f / 256.0f);
    float dx = vx - mean, dy = vy - mean, dz = vz - mean, dw = vw - mean;
    float s2 = dx * dx + dy * dy + dz * dz + dw * dw;
    #pragma unroll
    for (int off = 16; off > 0; off >>= 1) s2 += __shfl_down_sync(0xffffffffu, s2, off);
    if ((q & 31) == 0) shv[slot][q >> 5] = s2;
    __syncthreads();
    float var = (shv[slot][0] + shv[slot][1]) * (1.0f / 256.0f);
    float r = rsqrtf(var + EPS_LN);
    float4 g4 = ((const float4*)gam)[q];
    float4 e4 = ((const float4*)bet)[q];
    float o0 = fmaf(dx * r, g4.x, e4.x);
    float o1 = fmaf(dy * r, g4.y, e4.y);
    float o2 = fmaf(dz * r, g4.z, e4.z);
    float o3 = fmaf(dw * r, g4.w, e4.w);

    __nv_bfloat16 h0, l0, h1, l1, h2, l2, h3, l3;
    bsplit(o0, h0, l0); bsplit(o1, h1, l1); bsplit(o2, h2, l2); bsplit(o3, h3, l3);
    __nv_bfloat162* p1 = (__nv_bfloat162*)g_A1;
    __nv_bfloat162* p2 = (__nv_bfloat162*)g_A2;
    size_t bi = (size_t)node * 128 + q * 2;
    p1[bi]     = __halves2bfloat162(h0, h1);
    p1[bi + 1] = __halves2bfloat162(h2, h3);
    p2[bi]     = __halves2bfloat162(l0, l1);
    p2[bi + 1] = __halves2bfloat162(l2, l3);
}

// ---------------- final aggregate + bias + output + pool -----------------
__global__ void __launch_bounds__(256)
k_agg_out(const float* __restrict__ Y, const float* __restrict__ bias,
          const int* __restrict__ batch, float* __restrict__ out_h,
          float* __restrict__ pooled) {
    int slot = threadIdx.x >> 5;
    int q = threadIdx.x & 31;
    int node = (blockIdx.x << 3) + slot;
    int s0 = g_rowstart[node], c = g_cnt[node];
    float disi = rsqrtf((float)c + 1.0f);
    const float4* Yv = (const float4*)Y;

    float4 a = Yv[(size_t)node * 32 + q];
    float ax = a.x, ay = a.y, az = a.z, aw = a.w;
    int k = 0;
    for (; k + 8 <= c; k += 8) {
        int s[8];
        #pragma unroll
        for (int j = 0; j < 8; j++) s[j] = g_srcs[s0 + k + j];
        float4 y[8];
        #pragma unroll
        for (int j = 0; j < 8; j++) y[j] = Yv[(size_t)s[j] * 32 + q];
        #pragma unroll
        for (int j = 0; j < 8; j++) {
            ax += y[j].x; ay += y[j].y; az += y[j].z; aw += y[j].w;
        }
    }
    for (; k < c; k++) {
        float4 y = Yv[(size_t)g_srcs[s0 + k] * 32 + q];
        ax += y.x; ay += y.y; az += y.z; aw += y.w;
    }
    float4 b4 = ((const float4*)bias)[q];
    float4 v = make_float4(fmaf(disi, ax, b4.x), fmaf(disi, ay, b4.y),
                           fmaf(disi, az, b4.z), fmaf(disi, aw, b4.w));
    ((float4*)out_h)[(size_t)node * 32 + q] = v;
    float* pp = pooled + (size_t)batch[node] * DOUT + q * 4;
    atomicAdd(pp + 0, v.x);
    atomicAdd(pp + 1, v.y);
    atomicAdd(pp + 2, v.z);
    atomicAdd(pp + 3, v.w);
}

__global__ void k_pool_div(float* __restrict__ pooled) {
    int i = blockIdx.x * blockDim.x + threadIdx.x;
    if (i < NGR * DOUT) {
        float cnt = g_gcnt[i >> 7];
        pooled[i] = pooled[i] / fmaxf(cnt, 1.0f);
    }
}

// ---------------- host ---------------------------------------------------
#define GEMM_SMEM 65536

extern "C" void kernel_launch(void* const* d_in, const int* in_sizes, int n_in,
                              void* d_out, int out_size) {
    const float* x    = (const float*)d_in[0];
    const int*   ei   = (const int*)d_in[1];
    const int*   bat  = (const int*)d_in[2];
    const float* W1   = (const float*)d_in[3];
    const float* b1   = (const float*)d_in[4];
    const float* g1   = (const float*)d_in[5];
    const float* be1  = (const float*)d_in[6];
    const float* W2   = (const float*)d_in[7];
    const float* b2   = (const float*)d_in[8];
    const float* g2   = (const float*)d_in[9];
    const float* be2  = (const float*)d_in[10];
    const float* W3   = (const float*)d_in[11];
    const float* b3   = (const float*)d_in[12];

    float* out_h    = (float*)d_out;
    float* out_pool = out_h + (size_t)NN * DOUT;

    float* pY = nullptr;
    __nv_bfloat16 *pA1 = nullptr, *pA2 = nullptr;
    __nv_bfloat16 *pW1a = nullptr, *pW1b = nullptr, *pW2a = nullptr, *pW2b = nullptr;
    __nv_bfloat16 *pW3a = nullptr, *pW3b = nullptr;
    cudaGetSymbolAddress((void**)&pY,   g_bufY);
    cudaGetSymbolAddress((void**)&pA1,  g_A1);
    cudaGetSymbolAddress((void**)&pA2,  g_A2);
    cudaGetSymbolAddress((void**)&pW1a, g_Wt1a);
    cudaGetSymbolAddress((void**)&pW1b, g_Wt1b);
    cudaGetSymbolAddress((void**)&pW2a, g_Wt2a);
    cudaGetSymbolAddress((void**)&pW2b, g_Wt2b);
    cudaGetSymbolAddress((void**)&pW3a, g_Wt3a);
    cudaGetSymbolAddress((void**)&pW3b, g_Wt3b);

    cudaFuncSetAttribute(k_gemm<256>, cudaFuncAttributeMaxDynamicSharedMemorySize, GEMM_SMEM);
    cudaFuncSetAttribute(k_gemm<128>, cudaFuncAttributeMaxDynamicSharedMemorySize, GEMM_SMEM);

    // 0-2: prep so gemm1 (launch 3) can scale by dis in its epilogue
    k_splitW_init<<<dim3(256, 3), 256>>>(W1, W2, W3, out_pool);
    k_splitX_gc<<<(NN * DIN / 4) / 256, 256>>>(x, bat);
    k_deg<<<EE / 256, 256>>>(ei);

    // 3: layer-1 GEMM (profiled)
    k_gemm<256><<<dim3(2, NN / 128), 256, GEMM_SMEM>>>(pA1, pA2, pW1a, pW1b, pY);

    // CSR build
    k_scan1<<<64, 1024>>>();
    k_scan2<<<1, 32>>>();
    k_scan3<<<NN / 256, 256>>>();
    k_scatter<<<EE / 256, 256>>>(ei);

    // layer 1 aggregate -> relu -> LN -> bf16 splits
    k_agg_ln<<<NN / 4, 256>>>(pY, b1, g1, be1);
    // layer 2
    k_gemm<256><<<dim3(2, NN / 128), 256, GEMM_SMEM>>>(pA1, pA2, pW2a, pW2b, pY);
    k_agg_ln<<<NN / 4, 256>>>(pY, b2, g2, be2);
    // layer 3
    k_gemm<128><<<dim3(1, NN / 128), 256, GEMM_SMEM>>>(pA1, pA2, pW3a, pW3b, pY);
    k_agg_out<<<NN / 8, 256>>>(pY, b3, bat, out_h, out_pool);
    k_pool_div<<<(NGR * DOUT + 255) / 256, 256>>>(out_pool);
}

// round 5
// speedup vs baseline: 2.3327x; 1.1108x over previous
#include <cuda_runtime.h>
#include <cuda_bf16.h>
#include <cuda_fp16.h>
#include <math.h>
#include <stdint.h>

#define NN   65536
#define EE   1048576
#define NGR  64
#define DIN  256
#define DH   256
#define DOUT 128
#define EPS_LN 1e-5f

// ---------------- device scratch ----------------
__device__ __half g_bufY[(size_t)NN * DH];           // GEMM output (fp16, pre-scaled by dis)
__device__ __nv_bfloat16 g_A1[(size_t)NN * DH];      // GEMM input split hi
__device__ __nv_bfloat16 g_A2[(size_t)NN * DH];      // GEMM input split lo
__device__ __nv_bfloat16 g_Wt1a[256 * 256], g_Wt1b[256 * 256];
__device__ __nv_bfloat16 g_Wt2a[256 * 256], g_Wt2b[256 * 256];
__device__ __nv_bfloat16 g_Wt3a[128 * 256], g_Wt3b[128 * 256];
__device__ int   g_cnt[NN];          // in-degree (excl self loop); deg = cnt+1
__device__ int   g_rowstart[NN];
__device__ int   g_fill[NN];
__device__ int   g_srcs[EE];
__device__ int   g_part[64];
__device__ float g_gcnt[NGR];

// ======================= helpers ========================================
__device__ __forceinline__ uint32_t smem_u32(const void* p) {
    uint32_t a;
    asm("{ .reg .u64 t; cvta.to.shared.u64 t, %1; cvt.u32.u64 %0, t; }" : "=r"(a) : "l"(p));
    return a;
}

__device__ __forceinline__ void ldmx4(uint32_t* r, uint32_t addr) {
    asm volatile("ldmatrix.sync.aligned.m8n8.x4.shared.b16 {%0,%1,%2,%3}, [%4];"
                 : "=r"(r[0]), "=r"(r[1]), "=r"(r[2]), "=r"(r[3]) : "r"(addr));
}

__device__ __forceinline__ void mma16816(float* d, const uint32_t* a, uint32_t b0, uint32_t b1) {
    asm volatile(
        "mma.sync.aligned.m16n8k16.row.col.f32.bf16.bf16.f32 "
        "{%0,%1,%2,%3}, {%4,%5,%6,%7}, {%8,%9}, {%0,%1,%2,%3};"
        : "+f"(d[0]), "+f"(d[1]), "+f"(d[2]), "+f"(d[3])
        : "r"(a[0]), "r"(a[1]), "r"(a[2]), "r"(a[3]), "r"(b0), "r"(b1));
}

__device__ __forceinline__ void cp16(uint32_t dst, const void* src) {
    asm volatile("cp.async.cg.shared.global [%0], [%1], 16;" :: "r"(dst), "l"(src));
}
#define CP_COMMIT() asm volatile("cp.async.commit_group;" ::: "memory")

__device__ __forceinline__ void bsplit(float v, __nv_bfloat16& h, __nv_bfloat16& l) {
    h = __float2bfloat16(v);
    l = __float2bfloat16(v - __bfloat162float(h));
}

__device__ __forceinline__ void addh8(float* a, uint4 v) {
    __half2* h = (__half2*)&v;
    #pragma unroll
    for (int t = 0; t < 4; t++) {
        float2 f = __half22float2(h[t]);
        a[2 * t] += f.x;
        a[2 * t + 1] += f.y;
    }
}

__device__ __forceinline__ void addh4(float* a, uint2 v) {
    __half2* h = (__half2*)&v;
    #pragma unroll
    for (int t = 0; t < 2; t++) {
        float2 f = __half22float2(h[t]);
        a[2 * t] += f.x;
        a[2 * t + 1] += f.y;
    }
}

// ---------------- split W + zero counters/pooled -------------------------
__global__ void k_splitW_init(const float* __restrict__ W1, const float* __restrict__ W2,
                              const float* __restrict__ W3, float* pooled) {
    int l = blockIdx.y;
    int Nl = (l == 2) ? 128 : 256;
    int id = blockIdx.x * 256 + threadIdx.x;
    if (l == 0) {
        g_cnt[id] = 0;
        g_fill[id] = 0;
        if (id < NGR * DOUT) pooled[id] = 0.0f;
        if (id < NGR) g_gcnt[id] = 0.0f;
    }
    if (id >= Nl * 256) return;
    int n = id >> 8, k = id & 255;
    const float* W = (l == 0) ? W1 : (l == 1) ? W2 : W3;
    float v = W[k * Nl + n];
    __nv_bfloat16 h, lo; bsplit(v, h, lo);
    if (l == 0) { g_Wt1a[id] = h; g_Wt1b[id] = lo; }
    else if (l == 1) { g_Wt2a[id] = h; g_Wt2b[id] = lo; }
    else { g_Wt3a[id] = h; g_Wt3b[id] = lo; }
}

// ---------------- split x + graph-count atomics --------------------------
__global__ void k_splitX_gc(const float* __restrict__ X, const int* __restrict__ batch) {
    int i = blockIdx.x * blockDim.x + threadIdx.x;
    float4 v = ((const float4*)X)[i];
    __nv_bfloat16 h0, l0, h1, l1, h2, l2, h3, l3;
    bsplit(v.x, h0, l0); bsplit(v.y, h1, l1); bsplit(v.z, h2, l2); bsplit(v.w, h3, l3);
    __nv_bfloat162* p1 = (__nv_bfloat162*)g_A1;
    __nv_bfloat162* p2 = (__nv_bfloat162*)g_A2;
    p1[i * 2]     = __halves2bfloat162(h0, h1);
    p1[i * 2 + 1] = __halves2bfloat162(h2, h3);
    p2[i * 2]     = __halves2bfloat162(l0, l1);
    p2[i * 2 + 1] = __halves2bfloat162(l2, l3);
    if (i < NN) atomicAdd(&g_gcnt[batch[i]], 1.0f);
}

// ---------------- degree --------------------------------------------------
__global__ void k_deg(const int* __restrict__ ei) {
    int e = blockIdx.x * blockDim.x + threadIdx.x;
    if (e < EE) atomicAdd(&g_cnt[ei[EE + e]], 1);
}

__global__ void k_scan1() {
    __shared__ int sh[1024];
    int t = threadIdx.x;
    int i = blockIdx.x * 1024 + t;
    int v = g_cnt[i];
    sh[t] = v; __syncthreads();
    for (int off = 1; off < 1024; off <<= 1) {
        int a = (t >= off) ? sh[t - off] : 0;
        __syncthreads();
        sh[t] += a;
        __syncthreads();
    }
    g_rowstart[i] = sh[t] - v;
    if (t == 1023) g_part[blockIdx.x] = sh[t];
}

__global__ void k_scan2() {
    if (threadIdx.x == 0) {
        int run = 0;
        for (int b = 0; b < 64; b++) { int v = g_part[b]; g_part[b] = run; run += v; }
    }
}

__global__ void k_scan3() {
    int i = blockIdx.x * blockDim.x + threadIdx.x;
    if (i < NN) g_rowstart[i] += g_part[i >> 10];
}

__global__ void k_scatter(const int* __restrict__ ei) {
    int e = blockIdx.x * blockDim.x + threadIdx.x;
    if (e < EE) {
        int s = ei[e];
        int d = ei[EE + e];
        int pos = g_rowstart[d] + atomicAdd(&g_fill[d], 1);
        g_srcs[pos] = s;
    }
}

// ======================= HMMA bf16x3 GEMM (3-stage cp.async) ============
// C[65536, NMAT] (fp16) = dis[row] * (A[65536,256] @ W[256,NMAT])
// Block 128x128x32, 8 warps. smem: 3 stages x 32KB.
template <int NMAT>
__global__ void __launch_bounds__(256, 2)
k_gemm(const __nv_bfloat16* __restrict__ A1, const __nv_bfloat16* __restrict__ A2,
       const __nv_bfloat16* __restrict__ B1, const __nv_bfloat16* __restrict__ B2,
       __half* __restrict__ C) {
    extern __shared__ __align__(16) __nv_bfloat16 smem[];
    uint32_t sbase = smem_u32(smem);

    int tid = threadIdx.x;
    int lane = tid & 31;
    int wid = tid >> 5;
    int wm = wid & 3;
    int wn = wid >> 2;
    int mtile = blockIdx.y, ntile = blockIdx.x;

    float acc[2][8][4];
    #pragma unroll
    for (int i = 0; i < 2; i++)
        #pragma unroll
        for (int j = 0; j < 8; j++)
            #pragma unroll
            for (int q = 0; q < 4; q++) acc[i][j][q] = 0.0f;

    int r0i = tid >> 2, c0i = tid & 3;
    int r1i = (tid + 256) >> 2, c1i = (tid + 256) & 3;
    int sw0 = c0i ^ ((r0i >> 1) & 3), sw1 = c1i ^ ((r1i >> 1) & 3);
    uint32_t d0 = (r0i * 4 + sw0) * 16, d1 = (r1i * 4 + sw1) * 16;

    const uint4* pA1_0 = (const uint4*)A1 + (size_t)(mtile * 128 + r0i) * 32 + c0i;
    const uint4* pA1_1 = (const uint4*)A1 + (size_t)(mtile * 128 + r1i) * 32 + c1i;
    const uint4* pA2_0 = (const uint4*)A2 + (size_t)(mtile * 128 + r0i) * 32 + c0i;
    const uint4* pA2_1 = (const uint4*)A2 + (size_t)(mtile * 128 + r1i) * 32 + c1i;
    const uint4* pB1_0 = (const uint4*)B1 + (size_t)(ntile * 128 + r0i) * 32 + c0i;
    const uint4* pB1_1 = (const uint4*)B1 + (size_t)(ntile * 128 + r1i) * 32 + c1i;
    const uint4* pB2_0 = (const uint4*)B2 + (size_t)(ntile * 128 + r0i) * 32 + c0i;
    const uint4* pB2_1 = (const uint4*)B2 + (size_t)(ntile * 128 + r1i) * 32 + c1i;

    int lrow = lane & 15;
    int lhalf = lane >> 4;

    auto prefetch = [&](int st, int kc) {
        uint32_t sb = sbase + st * 32768;
        int ko = kc * 4;
        cp16(sb + d0,         pA1_0 + ko);
        cp16(sb + d1,         pA1_1 + ko);
        cp16(sb + 8192 + d0,  pA2_0 + ko);
        cp16(sb + 8192 + d1,  pA2_1 + ko);
        cp16(sb + 16384 + d0, pB1_0 + ko);
        cp16(sb + 16384 + d1, pB1_1 + ko);
        cp16(sb + 24576 + d0, pB2_0 + ko);
        cp16(sb + 24576 + d1, pB2_1 + ko);
    };

    prefetch(0, 0);
    CP_COMMIT();
    prefetch(1, 1);
    CP_COMMIT();

    #pragma unroll 1
    for (int kc = 0; kc < 8; kc++) {
        // wait for group kc to land: pending after this <= min(1, 7-kc)
        if (kc < 7) {
            asm volatile("cp.async.wait_group 1;" ::: "memory");
        } else {
            asm volatile("cp.async.wait_group 0;" ::: "memory");
        }
        __syncthreads();
        // prefetch kc+2 into buffer (kc+2)%3 == (kc-1)%3 (safe: sync above)
        if (kc < 6) {
            prefetch((kc + 2) % 3, kc + 2);
            CP_COMMIT();
        }

        uint32_t tb = sbase + (kc % 3) * 32768;
        #pragma unroll
        for (int ks = 0; ks < 2; ks++) {
            uint32_t a1[2][4], a2[2][4];
            #pragma unroll
            for (int mi = 0; mi < 2; mi++) {
                int row = wm * 32 + mi * 16 + lrow;
                int ch = (ks * 2 + lhalf) ^ ((row >> 1) & 3);
                uint32_t off = row * 64 + ch * 16;
                ldmx4(a1[mi], tb + off);
                ldmx4(a2[mi], tb + 8192 + off);
            }
            #pragma unroll
            for (int nh = 0; nh < 2; nh++) {
                uint32_t b1[2][4], b2[2][4];
                #pragma unroll
                for (int ni2 = 0; ni2 < 2; ni2++) {
                    int row = wn * 64 + nh * 32 + ni2 * 16 + lrow;
                    int ch = (ks * 2 + lhalf) ^ ((row >> 1) & 3);
                    uint32_t off = row * 64 + ch * 16;
                    ldmx4(b1[ni2], tb + 16384 + off);
                    ldmx4(b2[ni2], tb + 24576 + off);
                }
                #pragma unroll
                for (int mi = 0; mi < 2; mi++) {
                    #pragma unroll
                    for (int ni = 0; ni < 4; ni++) {
                        int ni2 = ni >> 1, nj = ni & 1;
                        float* d = acc[mi][nh * 4 + ni];
                        mma16816(d, a1[mi], b1[ni2][nj], b1[ni2][nj + 2]);
                        mma16816(d, a1[mi], b2[ni2][nj], b2[ni2][nj + 2]);
                        mma16816(d, a2[mi], b1[ni2][nj], b1[ni2][nj + 2]);
                    }
                }
            }
        }
    }

    // ---- epilogue: scale by dis[row] = rsqrt(cnt+1), write fp16 ----
    int crow0 = mtile * 128 + wm * 32 + (lane >> 2);
    int ccol0 = ntile * 128 + wn * 64 + (lane & 3) * 2;
    float dr[2][2];
    #pragma unroll
    for (int mi = 0; mi < 2; mi++) {
        dr[mi][0] = rsqrtf((float)g_cnt[crow0 + mi * 16] + 1.0f);
        dr[mi][1] = rsqrtf((float)g_cnt[crow0 + mi * 16 + 8] + 1.0f);
    }
    #pragma unroll
    for (int mi = 0; mi < 2; mi++) {
        #pragma unroll
        for (int ni = 0; ni < 8; ni++) {
            float* d = acc[mi][ni];
            int col = ccol0 + ni * 8;
            int r0 = crow0 + mi * 16;
            *(__half2*)(C + (size_t)r0 * NMAT + col) =
                __floats2half2_rn(d[0] * dr[mi][0], d[1] * dr[mi][0]);
            *(__half2*)(C + (size_t)(r0 + 8) * NMAT + col) =
                __floats2half2_rn(d[2] * dr[mi][1], d[3] * dr[mi][1]);
        }
    }
}

// ---------------- aggregate (fp16 in, warp per node) + relu + LN ---------
// 256 threads = 8 warps = 8 nodes/block; lane q holds features [q*8, q*8+8)
__global__ void __launch_bounds__(256)
k_agg_ln(const __half* __restrict__ Y,
         const float* __restrict__ bias, const float* __restrict__ gam,
         const float* __restrict__ bet) {
    int q = threadIdx.x & 31;
    int node = blockIdx.x * 8 + (threadIdx.x >> 5);
    int s0 = g_rowstart[node], c = g_cnt[node];
    float disi = rsqrtf((float)c + 1.0f);
    const uint4* Yv = (const uint4*)Y;     // row = 32 uint4

    float acc[8];
    #pragma unroll
    for (int i = 0; i < 8; i++) acc[i] = 0.0f;
    addh8(acc, Yv[(size_t)node * 32 + q]);       // self term (pre-scaled)

    int k = 0;
    for (; k + 8 <= c; k += 8) {
        int s[8];
        #pragma unroll
        for (int j = 0; j < 8; j++) s[j] = g_srcs[s0 + k + j];
        uint4 y[8];
        #pragma unroll
        for (int j = 0; j < 8; j++) y[j] = Yv[(size_t)s[j] * 32 + q];
        #pragma unroll
        for (int j = 0; j < 8; j++) addh8(acc, y[j]);
    }
    for (; k < c; k++) addh8(acc, Yv[(size_t)g_srcs[s0 + k] * 32 + q]);

    float4 b4a = ((const float4*)bias)[q * 2];
    float4 b4b = ((const float4*)bias)[q * 2 + 1];
    float v[8];
    v[0] = fmaxf(fmaf(disi, acc[0], b4a.x), 0.0f);
    v[1] = fmaxf(fmaf(disi, acc[1], b4a.y), 0.0f);
    v[2] = fmaxf(fmaf(disi, acc[2], b4a.z), 0.0f);
    v[3] = fmaxf(fmaf(disi, acc[3], b4a.w), 0.0f);
    v[4] = fmaxf(fmaf(disi, acc[4], b4b.x), 0.0f);
    v[5] = fmaxf(fmaf(disi, acc[5], b4b.y), 0.0f);
    v[6] = fmaxf(fmaf(disi, acc[6], b4b.z), 0.0f);
    v[7] = fmaxf(fmaf(disi, acc[7], b4b.w), 0.0f);

    float s1 = 0.0f;
    #pragma unroll
    for (int i = 0; i < 8; i++) s1 += v[i];
    #pragma unroll
    for (int off = 16; off > 0; off >>= 1) s1 += __shfl_xor_sync(0xffffffffu, s1, off);
    float mean = s1 * (1.0f / 256.0f);

    float dv[8];
    float s2 = 0.0f;
    #pragma unroll
    for (int i = 0; i < 8; i++) { dv[i] = v[i] - mean; s2 += dv[i] * dv[i]; }
    #pragma unroll
    for (int off = 16; off > 0; off >>= 1) s2 += __shfl_xor_sync(0xffffffffu, s2, off);
    float r = rsqrtf(s2 * (1.0f / 256.0f) + EPS_LN);

    float4 g4a = ((const float4*)gam)[q * 2];
    float4 g4b = ((const float4*)gam)[q * 2 + 1];
    float4 e4a = ((const float4*)bet)[q * 2];
    float4 e4b = ((const float4*)bet)[q * 2 + 1];
    float o[8];
    o[0] = fmaf(dv[0] * r, g4a.x, e4a.x);
    o[1] = fmaf(dv[1] * r, g4a.y, e4a.y);
    o[2] = fmaf(dv[2] * r, g4a.z, e4a.z);
    o[3] = fmaf(dv[3] * r, g4a.w, e4a.w);
    o[4] = fmaf(dv[4] * r, g4b.x, e4b.x);
    o[5] = fmaf(dv[5] * r, g4b.y, e4b.y);
    o[6] = fmaf(dv[6] * r, g4b.z, e4b.z);
    o[7] = fmaf(dv[7] * r, g4b.w, e4b.w);

    // bf16 splits packed as uint4 (8 bf16 each)
    uint4 hi, lo;
    __nv_bfloat162 hh[4], ll[4];
    #pragma unroll
    for (int t = 0; t < 4; t++) {
        __nv_bfloat16 h0, l0, h1, l1;
        bsplit(o[2 * t], h0, l0);
        bsplit(o[2 * t + 1], h1, l1);
        hh[t] = __halves2bfloat162(h0, h1);
        ll[t] = __halves2bfloat162(l0, l1);
    }
    hi = *(uint4*)hh;
    lo = *(uint4*)ll;
    ((uint4*)g_A1)[(size_t)node * 32 + q] = hi;
    ((uint4*)g_A2)[(size_t)node * 32 + q] = lo;
}

// ---------------- final aggregate + bias + output + pool -----------------
// warp per node, lane q holds features [q*4, q*4+4)
__global__ void __launch_bounds__(256)
k_agg_out(const __half* __restrict__ Y, const float* __restrict__ bias,
          const int* __restrict__ batch, float* __restrict__ out_h,
          float* __restrict__ pooled) {
    int q = threadIdx.x & 31;
    int node = blockIdx.x * 8 + (threadIdx.x >> 5);
    int s0 = g_rowstart[node], c = g_cnt[node];
    float disi = rsqrtf((float)c + 1.0f);
    const uint2* Yv = (const uint2*)Y;     // row = 32 uint2

    float acc[4];
    #pragma unroll
    for (int i = 0; i < 4; i++) acc[i] = 0.0f;
    addh4(acc, Yv[(size_t)node * 32 + q]);

    int k = 0;
    for (; k + 8 <= c; k += 8) {
        int s[8];
        #pragma unroll
        for (int j = 0; j < 8; j++) s[j] = g_srcs[s0 + k + j];
        uint2 y[8];
        #pragma unroll
        for (int j = 0; j < 8; j++) y[j] = Yv[(size_t)s[j] * 32 + q];
        #pragma unroll
        for (int j = 0; j < 8; j++) addh4(acc, y[j]);
    }
    for (; k < c; k++) addh4(acc, Yv[(size_t)g_srcs[s0 + k] * 32 + q]);

    float4 b4 = ((const float4*)bias)[q];
    float4 v = make_float4(fmaf(disi, acc[0], b4.x), fmaf(disi, acc[1], b4.y),
                           fmaf(disi, acc[2], b4.z), fmaf(disi, acc[3], b4.w));
    ((float4*)out_h)[(size_t)node * 32 + q] = v;
    float* pp = pooled + (size_t)batch[node] * DOUT + q * 4;
    atomicAdd(pp + 0, v.x);
    atomicAdd(pp + 1, v.y);
    atomicAdd(pp + 2, v.z);
    atomicAdd(pp + 3, v.w);
}

__global__ void k_pool_div(float* __restrict__ pooled) {
    int i = blockIdx.x * blockDim.x + threadIdx.x;
    if (i < NGR * DOUT) {
        float cnt = g_gcnt[i >> 7];
        pooled[i] = pooled[i] / fmaxf(cnt, 1.0f);
    }
}

// ---------------- host ---------------------------------------------------
#define GEMM_SMEM 98304

extern "C" void kernel_launch(void* const* d_in, const int* in_sizes, int n_in,
                              void* d_out, int out_size) {
    const float* x    = (const float*)d_in[0];
    const int*   ei   = (const int*)d_in[1];
    const int*   bat  = (const int*)d_in[2];
    const float* W1   = (const float*)d_in[3];
    const float* b1   = (const float*)d_in[4];
    const float* g1   = (const float*)d_in[5];
    const float* be1  = (const float*)d_in[6];
    const float* W2   = (const float*)d_in[7];
    const float* b2   = (const float*)d_in[8];
    const float* g2   = (const float*)d_in[9];
    const float* be2  = (const float*)d_in[10];
    const float* W3   = (const float*)d_in[11];
    const float* b3   = (const float*)d_in[12];

    float* out_h    = (float*)d_out;
    float* out_pool = out_h + (size_t)NN * DOUT;

    __half* pY = nullptr;
    __nv_bfloat16 *pA1 = nullptr, *pA2 = nullptr;
    __nv_bfloat16 *pW1a = nullptr, *pW1b = nullptr, *pW2a = nullptr, *pW2b = nullptr;
    __nv_bfloat16 *pW3a = nullptr, *pW3b = nullptr;
    cudaGetSymbolAddress((void**)&pY,   g_bufY);
    cudaGetSymbolAddress((void**)&pA1,  g_A1);
    cudaGetSymbolAddress((void**)&pA2,  g_A2);
    cudaGetSymbolAddress((void**)&pW1a, g_Wt1a);
    cudaGetSymbolAddress((void**)&pW1b, g_Wt1b);
    cudaGetSymbolAddress((void**)&pW2a, g_Wt2a);
    cudaGetSymbolAddress((void**)&pW2b, g_Wt2b);
    cudaGetSymbolAddress((void**)&pW3a, g_Wt3a);
    cudaGetSymbolAddress((void**)&pW3b, g_Wt3b);

    cudaFuncSetAttribute(k_gemm<256>, cudaFuncAttributeMaxDynamicSharedMemorySize, GEMM_SMEM);
    cudaFuncSetAttribute(k_gemm<128>, cudaFuncAttributeMaxDynamicSharedMemorySize, GEMM_SMEM);

    // 0-2: prep (gemm1 at launch 3 for the profiler window)
    k_splitW_init<<<dim3(256, 3), 256>>>(W1, W2, W3, out_pool);
    k_splitX_gc<<<(NN * DIN / 4) / 256, 256>>>(x, bat);
    k_deg<<<EE / 256, 256>>>(ei);

    // 3: layer-1 GEMM
    k_gemm<256><<<dim3(2, NN / 128), 256, GEMM_SMEM>>>(pA1, pA2, pW1a, pW1b, pY);

    // CSR build
    k_scan1<<<64, 1024>>>();
    k_scan2<<<1, 32>>>();
    k_scan3<<<NN / 256, 256>>>();
    k_scatter<<<EE / 256, 256>>>(ei);

    // layer 1 aggregate -> relu -> LN -> bf16 splits
    k_agg_ln<<<NN / 8, 256>>>(pY, b1, g1, be1);
    // layer 2
    k_gemm<256><<<dim3(2, NN / 128), 256, GEMM_SMEM>>>(pA1, pA2, pW2a, pW2b, pY);
    k_agg_ln<<<NN / 8, 256>>>(pY, b2, g2, be2);
    // layer 3
    k_gemm<128><<<dim3(1, NN / 128), 256, GEMM_SMEM>>>(pA1, pA2, pW3a, pW3b, pY);
    k_agg_out<<<NN / 8, 256>>>(pY, b3, bat, out_h, out_pool);
    k_pool_div<<<(NGR * DOUT + 255) / 256, 256>>>(out_pool);
}